// round 17
// baseline (speedup 1.0000x reference)
#include <cuda_runtime.h>
#include <cuda_bf16.h>
#include <cstdint>

// ---------------- problem dims (fixed by setup_inputs) ----------------
#define DIN   4096
#define DOUT  4096
#define TMAX  8192

// ---------------- scratch (device globals: alloc-free rule) -----------
__device__ __align__(1024) char g_q [(size_t)TMAX * DIN];   // 32 MB int8 activations (exact)
__device__ __align__(1024) char g_w1[(size_t)DOUT * DIN];   // 16 MB int8 W plane 1
__device__ __align__(1024) char g_w2[(size_t)DOUT * DIN];   // 16 MB int8 W plane 2 (residual*128/a)
__device__ float g_ts[TMAX];                                 // per-token act scale
__device__ float g_wa[DOUT];                                 // per-row weight scale a_n

// ============================================================================
// Kernel 1: 2:4 activation sparsity + per-token absmax quant -> q (int8), scale
// ============================================================================
__global__ void __launch_bounds__(128) prep_kernel(const float* __restrict__ x,
                                                   const float* __restrict__ ss) {
    int t = blockIdx.x;
    int tid = threadIdx.x;
    const float4* xr = reinterpret_cast<const float4*>(x + (size_t)t * DIN);
    const float4* sr = reinterpret_cast<const float4*>(ss);

    float4 v[8];
    float amax = 0.f;
#pragma unroll
    for (int j = 0; j < 8; ++j) {
        int g = tid + j * 128;                 // one group of 4 columns
        float4 xv = xr[g];
        float4 sv = __ldg(sr + g);
        float a0 = fabsf(xv.x) * sv.x;
        float a1 = fabsf(xv.y) * sv.y;
        float a2 = fabsf(xv.z) * sv.z;
        float a3 = fabsf(xv.w) * sv.w;
        // rank(j) = #{i : m_i < m_j or (m_i == m_j and i < j)}; zero if rank < 2
        int r0 = (a1 <  a0) + (a2 <  a0) + (a3 <  a0);
        int r1 = (a0 <= a1) + (a2 <  a1) + (a3 <  a1);
        int r2 = (a0 <= a2) + (a1 <= a2) + (a3 <  a2);
        int r3 = (a0 <= a3) + (a1 <= a3) + (a2 <= a3);
        xv.x = (r0 >= 2) ? xv.x : 0.f;
        xv.y = (r1 >= 2) ? xv.y : 0.f;
        xv.z = (r2 >= 2) ? xv.z : 0.f;
        xv.w = (r3 >= 2) ? xv.w : 0.f;
        v[j] = xv;
        amax = fmaxf(amax, fmaxf(fmaxf(fabsf(xv.x), fabsf(xv.y)),
                                 fmaxf(fabsf(xv.z), fabsf(xv.w))));
    }
#pragma unroll
    for (int o = 16; o > 0; o >>= 1)
        amax = fmaxf(amax, __shfl_xor_sync(0xffffffffu, amax, o));
    __shared__ float red[4];
    if ((tid & 31) == 0) red[tid >> 5] = amax;
    __syncthreads();
    float am = fmaxf(fmaxf(red[0], red[1]), fmaxf(red[2], red[3]));
    float s = fmaxf(am, 1e-5f) / 127.0f;       // same op order as reference
    if (tid == 0) g_ts[t] = s;

    uint32_t* qr = reinterpret_cast<uint32_t*>(g_q + (size_t)t * DIN);
#pragma unroll
    for (int j = 0; j < 8; ++j) {
        int g = tid + j * 128;
        float4 xv = v[j];
        int q0 = (int)rintf(__fdiv_rn(xv.x, s));
        int q1 = (int)rintf(__fdiv_rn(xv.y, s));
        int q2 = (int)rintf(__fdiv_rn(xv.z, s));
        int q3 = (int)rintf(__fdiv_rn(xv.w, s));
        qr[g] = (q0 & 0xff) | ((q1 & 0xff) << 8) | ((q2 & 0xff) << 16)
              | ((uint32_t)(q3 & 0xff) << 24);
    }
}

// ============================================================================
// Kernel 2: per-row dual-plane int8 weight quant
//   a_n = rowmax/127 ; W1 = rint(W/a) ; W2 = rint((W - a*W1)*128/a)
//   => W ~= a*(W1 + W2/128), residual <= a/256  (~1e-4 output rel err)
// ============================================================================
__global__ void __launch_bounds__(128) wquant_kernel(const float* __restrict__ w) {
    int n = blockIdx.x;
    int tid = threadIdx.x;
    const float4* wr = reinterpret_cast<const float4*>(w + (size_t)n * DIN);

    float4 v[8];
    float amax = 0.f;
#pragma unroll
    for (int j = 0; j < 8; ++j) {
        v[j] = wr[tid + j * 128];
        amax = fmaxf(amax, fmaxf(fmaxf(fabsf(v[j].x), fabsf(v[j].y)),
                                 fmaxf(fabsf(v[j].z), fabsf(v[j].w))));
    }
#pragma unroll
    for (int o = 16; o > 0; o >>= 1)
        amax = fmaxf(amax, __shfl_xor_sync(0xffffffffu, amax, o));
    __shared__ float red[4];
    if ((tid & 31) == 0) red[tid >> 5] = amax;
    __syncthreads();
    float am = fmaxf(fmaxf(red[0], red[1]), fmaxf(red[2], red[3]));
    float a = fmaxf(am, 1e-30f) / 127.0f;
    if (tid == 0) g_wa[n] = a;
    float inva  = 1.0f / a;
    float inv2  = 128.0f / a;

    uint32_t* o1 = reinterpret_cast<uint32_t*>(g_w1 + (size_t)n * DIN);
    uint32_t* o2 = reinterpret_cast<uint32_t*>(g_w2 + (size_t)n * DIN);
#pragma unroll
    for (int j = 0; j < 8; ++j) {
        int g = tid + j * 128;
        float4 wv = v[j];
        int p1[4], p2[4];
        float e[4] = {wv.x, wv.y, wv.z, wv.w};
#pragma unroll
        for (int c = 0; c < 4; ++c) {
            int i1 = (int)rintf(e[c] * inva);
            float r = e[c] - a * (float)i1;
            int i2 = (int)rintf(r * inv2);      // |i2| <= ~65 fits s8
            p1[c] = i1; p2[c] = i2;
        }
        o1[g] = (p1[0] & 0xff) | ((p1[1] & 0xff) << 8) | ((p1[2] & 0xff) << 16)
              | ((uint32_t)(p1[3] & 0xff) << 24);
        o2[g] = (p2[0] & 0xff) | ((p2[1] & 0xff) << 8) | ((p2[2] & 0xff) << 16)
              | ((uint32_t)(p2[3] & 0xff) << 24);
    }
}

// ============================================================================
// Kernel 3: int8 dual-plane GEMM (cp.async + ldmatrix + mma.m16n8k32.s8)
//   CTA 128x128, BK=64, 4 stages x 24KB, 512 thr (16 warps, 4x4 grid of 32x32)
//   out[m][n] = ts[m]*a[n]*(P1 + P2/128) + bias[n]
// ============================================================================
#define BK       64
#define KIT      (DIN / BK)            // 64
#define STG      4
#define STAGE_A  8192                  // 128 rows x 64B (paired-row swizzled)
#define STAGE_BB 16384                 // 128 rows x 128B (plane-interleaved)
#define STAGE_SZ (STAGE_A + STAGE_BB)  // 24576
#define SMEM_SZ  (STG * STAGE_SZ)      // 98304

__device__ __forceinline__ uint32_t smem_u32(const void* p) {
    uint32_t a;
    asm("{ .reg .u64 t; cvta.to.shared.u64 t, %1; cvt.u32.u64 %0, t; }" : "=r"(a) : "l"(p));
    return a;
}
__device__ __forceinline__ void cp16(uint32_t dst, const void* src) {
    asm volatile("cp.async.cg.shared.global [%0], [%1], 16;" :: "r"(dst), "l"(src));
}
#define CP_COMMIT() asm volatile("cp.async.commit_group;" ::: "memory")
#define CP_WAIT2()  asm volatile("cp.async.wait_group 2;" ::: "memory")

#define LDSM4(r, addr) \
    asm volatile("ldmatrix.sync.aligned.m8n8.x4.shared.b16 {%0,%1,%2,%3}, [%4];" \
        : "=r"((r)[0]), "=r"((r)[1]), "=r"((r)[2]), "=r"((r)[3]) : "r"(addr))

#define MMAS8(d, a, b0, b1) \
    asm volatile("mma.sync.aligned.m16n8k32.row.col.s32.s8.s8.s32 " \
        "{%0,%1,%2,%3}, {%4,%5,%6,%7}, {%8,%9}, {%0,%1,%2,%3};" \
        : "+r"((d)[0]), "+r"((d)[1]), "+r"((d)[2]), "+r"((d)[3]) \
        : "r"((a)[0]), "r"((a)[1]), "r"((a)[2]), "r"((a)[3]), "r"(b0), "r"(b1))

// A: 64B rows packed two-per-128B-line, XOR swizzle -> ldmatrix conflict-free
__device__ __forceinline__ uint32_t addrA(uint32_t m, uint32_t c) {
    return (m >> 1) * 128u + (m & 1u) * 64u + ((c ^ ((m >> 1) & 3u)) << 4);
}
// B: 128B rows = [plane0 64B | plane1 64B], classic 8-row XOR swizzle
__device__ __forceinline__ uint32_t addrB(uint32_t n, uint32_t c) {
    return n * 128u + ((c ^ (n & 7u)) << 4);
}

__global__ void __launch_bounds__(512, 1) gemm_kernel(const float* __restrict__ bias,
                                                      float* __restrict__ out) {
    extern __shared__ __align__(1024) char smem[];
    const uint32_t sb = smem_u32(smem);
    const int tid  = threadIdx.x;
    const int lane = tid & 31;
    const int wid  = tid >> 5;
    const int wm   = wid & 3;            // 4 warps along M (32 rows each)
    const int wn   = wid >> 2;           // 4 warps along N (32 cols each)
    const int n0   = blockIdx.x * 128;
    const int m0   = blockIdx.y * 128;

    // ---------- producer addressing (512 thr: 1 A-chunk + 2 B-chunks) ----------
    const int am_ = tid >> 2, ac_ = tid & 3;
    const char* srcA = g_q + (size_t)(m0 + am_) * DIN + ac_ * 16;
    const uint32_t dstA = addrA(am_, ac_);
    const int bn_ = tid >> 3, bc_ = tid & 7;
    const char* wplane = (bc_ >> 2) ? g_w2 : g_w1;
    const char* srcB0 = wplane + (size_t)(n0 + bn_)      * DIN + (bc_ & 3) * 16;
    const char* srcB1 = wplane + (size_t)(n0 + bn_ + 64) * DIN + (bc_ & 3) * 16;
    const uint32_t dstB0 = STAGE_A + addrB(bn_,      bc_);
    const uint32_t dstB1 = STAGE_A + addrB(bn_ + 64, bc_);

    // ---------- consumer (ldmatrix) per-lane offsets ----------
    const uint32_t j = (uint32_t)(lane & 7);
    uint32_t offA[2][2];   // [mt][ks]
#pragma unroll
    for (int mt = 0; mt < 2; ++mt)
#pragma unroll
        for (int ks = 0; ks < 2; ++ks) {
            uint32_t row = wm * 32 + mt * 16 + ((lane >> 3) & 1) * 8 + j;
            uint32_t c   = 2 * ks + (lane >> 4);
            offA[mt][ks] = addrA(row, c);
        }
    uint32_t offB[2][2][2];  // [ks][p][h]
#pragma unroll
    for (int ks = 0; ks < 2; ++ks)
#pragma unroll
        for (int p = 0; p < 2; ++p)
#pragma unroll
            for (int h = 0; h < 2; ++h) {
                uint32_t n = wn * 32 + h * 16 + ((lane >> 4) & 1) * 8 + j;
                uint32_t c = 4 * p + 2 * ks + ((lane >> 3) & 1);
                offB[ks][p][h] = STAGE_A + addrB(n, c);
            }

    int acc[2][2][4][4];     // [plane][mt][n8-group][4]
#pragma unroll
    for (int p = 0; p < 2; ++p)
#pragma unroll
        for (int mt = 0; mt < 2; ++mt)
#pragma unroll
            for (int g = 0; g < 4; ++g)
#pragma unroll
                for (int c = 0; c < 4; ++c) acc[p][mt][g][c] = 0;

    // ---------- prologue: fill 3 stages ----------
#pragma unroll
    for (int s = 0; s < STG - 1; ++s) {
        uint32_t st = sb + s * STAGE_SZ;
        int ko = s * BK;
        cp16(st + dstA,  srcA  + ko);
        cp16(st + dstB0, srcB0 + ko);
        cp16(st + dstB1, srcB1 + ko);
        CP_COMMIT();
    }

    // ---------- main loop: single sync, prefetch-after-sync ----------
#pragma unroll 1
    for (int kt = 0; kt < KIT; ++kt) {
        CP_WAIT2();
        __syncthreads();

        if (kt + STG - 1 < KIT) {
            uint32_t st = sb + ((kt + STG - 1) & (STG - 1)) * STAGE_SZ;
            int ko = (kt + STG - 1) * BK;
            cp16(st + dstA,  srcA  + ko);
            cp16(st + dstB0, srcB0 + ko);
            cp16(st + dstB1, srcB1 + ko);
        }
        CP_COMMIT();

        const uint32_t st = sb + (kt & (STG - 1)) * STAGE_SZ;
#pragma unroll
        for (int ks = 0; ks < 2; ++ks) {
            uint32_t a[2][4];
            LDSM4(a[0], st + offA[0][ks]);
            LDSM4(a[1], st + offA[1][ks]);
#pragma unroll
            for (int p = 0; p < 2; ++p) {
#pragma unroll
                for (int h = 0; h < 2; ++h) {
                    uint32_t b[4];
                    LDSM4(b, st + offB[ks][p][h]);
                    MMAS8(acc[p][0][2 * h],     a[0], b[0], b[1]);
                    MMAS8(acc[p][0][2 * h + 1], a[0], b[2], b[3]);
                    MMAS8(acc[p][1][2 * h],     a[1], b[0], b[1]);
                    MMAS8(acc[p][1][2 * h + 1], a[1], b[2], b[3]);
                }
            }
        }
    }

    // ---------- epilogue: y = ts[m]*a[n]*(P1 + P2/128) + bias[n] ----------
    const float inv128 = 0.0078125f;
#pragma unroll
    for (int mt = 0; mt < 2; ++mt) {
        int r = m0 + wm * 32 + mt * 16 + (lane >> 2);
        float t0 = g_ts[r];
        float t1 = g_ts[r + 8];
        float* o0 = out + (size_t)r * DOUT;
        float* o1 = o0 + (size_t)8 * DOUT;
#pragma unroll
        for (int g = 0; g < 4; ++g) {
            int n = n0 + wn * 32 + g * 8 + (lane & 3) * 2;
            float2 wa = *reinterpret_cast<const float2*>(g_wa + n);
            float2 bb = *reinterpret_cast<const float2*>(bias + n);
            float s00 = t0 * wa.x, s01 = t0 * wa.y;
            float s10 = t1 * wa.x, s11 = t1 * wa.y;
            float2 v0, v1;
            v0.x = s00 * ((float)acc[0][mt][g][0] + inv128 * (float)acc[1][mt][g][0]) + bb.x;
            v0.y = s01 * ((float)acc[0][mt][g][1] + inv128 * (float)acc[1][mt][g][1]) + bb.y;
            v1.x = s10 * ((float)acc[0][mt][g][2] + inv128 * (float)acc[1][mt][g][2]) + bb.x;
            v1.y = s11 * ((float)acc[0][mt][g][3] + inv128 * (float)acc[1][mt][g][3]) + bb.y;
            *reinterpret_cast<float2*>(o0 + n) = v0;
            *reinterpret_cast<float2*>(o1 + n) = v1;
        }
    }
}

// ============================================================================
// host launcher
// ============================================================================
extern "C" void kernel_launch(void* const* d_in, const int* in_sizes, int n_in,
                              void* d_out, int out_size) {
    const float* x    = (const float*)d_in[0];   // (B,S,DIN)
    const float* w    = (const float*)d_in[1];   // (DOUT,DIN)
    const float* bias = (const float*)d_in[2];   // (1,DOUT)
    const float* ss   = (const float*)d_in[3];   // (1,DIN)
    float* out = (float*)d_out;
    int T = in_sizes[0] / DIN;                   // 8192 tokens

    static bool attr_set = false;
    if (!attr_set) {
        cudaFuncSetAttribute(gemm_kernel, cudaFuncAttributeMaxDynamicSharedMemorySize,
                             SMEM_SZ);
        attr_set = true;
    }

    prep_kernel<<<T, 128>>>(x, ss);
    wquant_kernel<<<DOUT, 128>>>(w);
    dim3 grid(DOUT / 128, T / 128);
    gemm_kernel<<<grid, 512, SMEM_SZ>>>(bias, out);
}